// round 10
// baseline (speedup 1.0000x reference)
#include <cuda_runtime.h>

#define N_PTS   524288            // = 1 << 19
#define PT_BITS 19
#define TBITS   19
#define TMASK   ((1u << TBITS) - 1u)
#define BLOCK   256
#define PPB     128
#define AS      100               // row stride: 100 ≡ 4 (mod 32) -> LDS.128 lanes tile banks
#define W_FLOATS 13576
#define SMEM_BYTES  (PPB * AS * 4)

// Feature-major hash-encode scratch: g_enc[f * N_PTS + pt], f in [0,32)
__device__ float g_enc[32u * N_PTS];

// Packed weights: staged in device scratch, then copied into the constant bank.
__device__ __align__(16) float g_wpack[W_FLOATS];
__constant__ __align__(16) float c_wpack[W_FLOATS];

// Packed-layout offsets (floats)
#define OFF_W0   0        // [64 out][8  q] float4
#define OFF_W1   2048     // [64 out][16 q] float4
#define OFF_W2   6144     // [64 out][16 q] float4
#define OFF_WRB  10240    // [32 out][16 q] float4  (wr rows 27..90)
#define OFF_WRD  12288    // [32 out][7  q] float4  (wr rows 0..26 + pad)
#define OFF_WC   13184    // [3][8 q] float4
#define OFF_WD   13280    // [16 q] float4
#define OFF_B0   13344
#define OFF_B1   13408
#define OFF_B2   13472
#define OFF_BR   13536
#define OFF_BC   13568
#define OFF_BD   13572

// Packed dual-FMA on float2 (sm_103a f32x2 pipe)
__device__ __forceinline__ float2 ffma2(float2 a, float2 b, float2 c) {
    float2 d;
    asm("fma.rn.f32x2 %0, %1, %2, %3;"
        : "=l"(reinterpret_cast<unsigned long long&>(d))
        : "l"(reinterpret_cast<unsigned long long&>(a)),
          "l"(reinterpret_cast<unsigned long long&>(b)),
          "l"(reinterpret_cast<unsigned long long&>(c)));
    return d;
}

__constant__ float c_scale[16] = {
    16.f, 21.f, 27.f, 36.f, 48.f, 64.f, 84.f, 111.f,
    147.f, 194.f, 256.f, 337.f, 445.f, 588.f, 776.f, 1024.f
};

// ===================== Kernel 0: repack weights into g_wpack =====================
__global__ __launch_bounds__(256) void repack_kernel(
    const float* __restrict__ w0, const float* __restrict__ b0,
    const float* __restrict__ w1, const float* __restrict__ b1,
    const float* __restrict__ w2, const float* __restrict__ b2,
    const float* __restrict__ wr, const float* __restrict__ br,
    const float* __restrict__ wc, const float* __restrict__ bc,
    const float* __restrict__ wd, const float* __restrict__ bd)
{
    float4* p_w0  = (float4*)(g_wpack + OFF_W0);
    float4* p_w1  = (float4*)(g_wpack + OFF_W1);
    float4* p_w2  = (float4*)(g_wpack + OFF_W2);
    float4* p_wrb = (float4*)(g_wpack + OFF_WRB);
    float4* p_wrd = (float4*)(g_wpack + OFF_WRD);
    float4* p_wc  = (float4*)(g_wpack + OFF_WC);
    float4* p_wd  = (float4*)(g_wpack + OFF_WD);
    const int t = threadIdx.x;
    for (int k = t; k < 64 * 8; k += 256) {
        int o = k >> 3, q = k & 7;
        p_w0[k] = make_float4(w0[(4*q  )*64 + o], w0[(4*q+1)*64 + o],
                              w0[(4*q+2)*64 + o], w0[(4*q+3)*64 + o]);
    }
    for (int k = t; k < 64 * 16; k += 256) {
        int o = k >> 4, q = k & 15;
        p_w1[k] = make_float4(w1[(4*q  )*64 + o], w1[(4*q+1)*64 + o],
                              w1[(4*q+2)*64 + o], w1[(4*q+3)*64 + o]);
        p_w2[k] = make_float4(w2[(4*q  )*64 + o], w2[(4*q+1)*64 + o],
                              w2[(4*q+2)*64 + o], w2[(4*q+3)*64 + o]);
    }
    for (int k = t; k < 32 * 16; k += 256) {
        int o = k >> 4, q = k & 15;
        p_wrb[k] = make_float4(wr[(27+4*q  )*32 + o], wr[(27+4*q+1)*32 + o],
                               wr[(27+4*q+2)*32 + o], wr[(27+4*q+3)*32 + o]);
    }
    for (int k = t; k < 32 * 7; k += 256) {
        int o = k / 7, q = k % 7;
        float a = wr[(4*q  )*32 + o];
        float b = wr[(4*q+1)*32 + o];
        float c = wr[(4*q+2)*32 + o];
        float d = (q == 6) ? 0.f : wr[(4*q+3)*32 + o];
        p_wrd[k] = make_float4(a, b, c, d);
    }
    for (int k = t; k < 3 * 8; k += 256) {
        int c = k >> 3, q = k & 7;
        p_wc[k] = make_float4(wc[(4*q  )*3 + c], wc[(4*q+1)*3 + c],
                              wc[(4*q+2)*3 + c], wc[(4*q+3)*3 + c]);
    }
    for (int k = t; k < 16; k += 256)
        p_wd[k] = make_float4(wd[4*k], wd[4*k+1], wd[4*k+2], wd[4*k+3]);
    for (int k = t; k < 64; k += 256) {
        g_wpack[OFF_B0 + k] = b0[k];
        g_wpack[OFF_B1 + k] = b1[k];
        g_wpack[OFF_B2 + k] = b2[k];
    }
    for (int k = t; k < 32; k += 256) g_wpack[OFF_BR + k] = br[k];
    if (t < 3) g_wpack[OFF_BC + t] = bc[t];
    if (t == 3) g_wpack[OFF_BC + 3] = 0.f;
    if (t == 0) g_wpack[OFF_BD] = bd[0];
}

// ===================== Kernel A: hash-grid encode =====================
__global__ __launch_bounds__(256) void encode_kernel(
    const float* __restrict__ pos, const float2* __restrict__ tab)
{
    const unsigned g  = blockIdx.x * 256u + threadIdx.x;
    const int      l  = (int)(g >> PT_BITS);       // 0..15
    const unsigned pt = g & (N_PTS - 1u);

    const float px = pos[3 * pt], py = pos[3 * pt + 1], pz = pos[3 * pt + 2];
    const float sc = c_scale[l];
    const float sx = px * sc, sy = py * sc, sz = pz * sc;
    const float fx = floorf(sx), fy = floorf(sy), fz = floorf(sz);
    const float ox = sx - fx, oy = sy - fy, oz = sz - fz;
    const unsigned hx0 = (unsigned)(int)fx;                 // x prime = 1
    const unsigned hx1 = (unsigned)(int)ceilf(sx);
    const unsigned hy0 = (unsigned)(int)fy * 2654435761u;
    const unsigned hy1 = (unsigned)(int)ceilf(sy) * 2654435761u;
    const unsigned hz0 = (unsigned)(int)fz * 805459861u;
    const unsigned hz1 = (unsigned)(int)ceilf(sz) * 805459861u;
    const unsigned lvl = ((unsigned)l) << TBITS;
    const float wx0 = 1.f - ox, wy0 = 1.f - oy, wz0 = 1.f - oz;

    float2 a = make_float2(0.f, 0.f);
    #pragma unroll
    for (int p = 0; p < 4; p++) {
        const unsigned hyz = ((p & 1) ? hy1 : hy0) ^ ((p & 2) ? hz1 : hz0);
        const unsigned i0 = (hx0 ^ hyz) & TMASK;
        const unsigned i1 = (hx1 ^ hyz) & TMASK;
        const float4 q = __ldg((const float4*)(tab + ((i0 & ~1u) + lvl)));
        const float2 lo = make_float2(q.x, q.y);
        const float2 hi = make_float2(q.z, q.w);
        float2 e0 = (i0 & 1u) ? hi : lo;
        float2 e1;
        if (i1 == (i0 ^ 1u)) {
            e1 = (i0 & 1u) ? lo : hi;
        } else {
            e1 = __ldg(&tab[i1 + lvl]);
        }
        const float wyz = ((p & 1) ? oy : wy0) * ((p & 2) ? oz : wz0);
        const float w0f = wx0 * wyz, w1f = ox * wyz;
        a = ffma2(make_float2(w0f, w0f), e0, a);
        a = ffma2(make_float2(w1f, w1f), e1, a);
    }
    g_enc[(2u * l)     * (unsigned)N_PTS + pt] = a.x;
    g_enc[(2u * l + 1) * (unsigned)N_PTS + pt] = a.y;
}

// ===================== Kernel B: MLP + heads (weights in constant) =====================
__global__ __launch_bounds__(BLOCK, 2) void mlp_kernel(
    const float* __restrict__ dir, float* __restrict__ out)
{
    extern __shared__ float buf[];          // [128][100] activation buffer only

    const float4* cw0  = (const float4*)(c_wpack + OFF_W0);
    const float4* cw1  = (const float4*)(c_wpack + OFF_W1);
    const float4* cw2  = (const float4*)(c_wpack + OFF_W2);
    const float4* cwrb = (const float4*)(c_wpack + OFF_WRB);
    const float4* cwrd = (const float4*)(c_wpack + OFF_WRD);
    const float4* cwc  = (const float4*)(c_wpack + OFF_WC);
    const float4* cwd  = (const float4*)(c_wpack + OFF_WD);
    const float*  cb0  = c_wpack + OFF_B0;
    const float*  cb1  = c_wpack + OFF_B1;
    const float*  cb2  = c_wpack + OFF_B2;
    const float*  cbr  = c_wpack + OFF_BR;
    const float*  cbc  = c_wpack + OFF_BC;
    const float*  cbd  = c_wpack + OFF_BD;

    const int t  = threadIdx.x;
    const int ib = blockIdx.x * PPB;

    // ---- Stage enc: coalesced LDG x4 -> one STS.128 ----
    for (int k = t; k < 8 * PPB; k += BLOCK) {
        const int fg = k >> 7;            // 0..7 -> f = 4*fg
        const int p  = k & (PPB - 1);
        const unsigned gp = (unsigned)(ib + p);
        const int f = 4 * fg;
        float4 v;
        v.x = g_enc[(unsigned)(f    ) * N_PTS + gp];
        v.y = g_enc[(unsigned)(f + 1) * N_PTS + gp];
        v.z = g_enc[(unsigned)(f + 2) * N_PTS + gp];
        v.w = g_enc[(unsigned)(f + 3) * N_PTS + gp];
        *(float4*)(buf + p * AS + f) = v;
    }

    // ---- Direction encode: 2 threads per point -> row[64..91] ----
    {
        const int pt = t & (PPB - 1);
        const int hf = t >> 7;
        const int i  = ib + pt;
        float* row = buf + pt * AS;
        const float fr[4] = {1.f, 2.5198421f, 6.3496042f, 16.f};
        if (hf == 0) {
            const float dx = dir[3 * i], dy = dir[3 * i + 1];
            const float tx = 6.2831855f * dx, ty = 6.2831855f * dy;
            #pragma unroll
            for (int k = 0; k < 4; k++) {
                float s, c;
                sincosf(tx * fr[k], &s, &c);
                row[64 + k] = s; row[64 + 12 + k] = c;
                sincosf(ty * fr[k], &s, &c);
                row[64 + 4 + k] = s; row[64 + 16 + k] = c;
            }
        } else {
            const float dx = dir[3 * i], dy = dir[3 * i + 1], dz = dir[3 * i + 2];
            const float tz = 6.2831855f * dz;
            #pragma unroll
            for (int k = 0; k < 4; k++) {
                float s, c;
                sincosf(tz * fr[k], &s, &c);
                row[64 + 8 + k] = s; row[64 + 20 + k] = c;
            }
            row[64 + 24] = dx; row[64 + 25] = dy; row[64 + 26] = dz;
            row[64 + 27] = 0.f;
        }
    }
    __syncthreads();

    // ================= MLP: warp-uniform quarter, 2 points/lane =============
    const int w    = t >> 5, lane = t & 31;
    const int qt   = w & 3;                 // warp-uniform (tid>>5 pattern)
    const int pg   = w >> 2;
    const int p0   = pg * 64 + lane;
    const int p1   = p0 + 32;
    float* r0 = buf + p0 * AS;
    float* r1 = buf + p1 * AS;

    float2 acc0[16], acc1[16];

    // ---------------- Layer 0: 32 -> 64, relu ----------------
    #pragma unroll
    for (int o = 0; o < 16; o++) { acc0[o] = make_float2(0.f,0.f); acc1[o] = make_float2(0.f,0.f); }
    #pragma unroll
    for (int c = 0; c < 4; c++) {
        const float4 qa0 = *(const float4*)(r0 + 8*c);
        const float4 qb0 = *(const float4*)(r0 + 8*c + 4);
        const float4 qa1 = *(const float4*)(r1 + 8*c);
        const float4 qb1 = *(const float4*)(r1 + 8*c + 4);
        const float2 a00 = make_float2(qa0.x,qa0.y), a01 = make_float2(qa0.z,qa0.w);
        const float2 a02 = make_float2(qb0.x,qb0.y), a03 = make_float2(qb0.z,qb0.w);
        const float2 a10 = make_float2(qa1.x,qa1.y), a11 = make_float2(qa1.z,qa1.w);
        const float2 a12 = make_float2(qb1.x,qb1.y), a13 = make_float2(qb1.z,qb1.w);
        #pragma unroll
        for (int o = 0; o < 16; o++) {
            const float4* wv = cw0 + (qt * 16 + o) * 8 + 2 * c;
            const float4 v0 = wv[0], v1 = wv[1];
            const float2 w0f = make_float2(v0.x,v0.y), w1f = make_float2(v0.z,v0.w);
            const float2 w2f = make_float2(v1.x,v1.y), w3f = make_float2(v1.z,v1.w);
            acc0[o] = ffma2(a00, w0f, acc0[o]); acc0[o] = ffma2(a01, w1f, acc0[o]);
            acc0[o] = ffma2(a02, w2f, acc0[o]); acc0[o] = ffma2(a03, w3f, acc0[o]);
            acc1[o] = ffma2(a10, w0f, acc1[o]); acc1[o] = ffma2(a11, w1f, acc1[o]);
            acc1[o] = ffma2(a12, w2f, acc1[o]); acc1[o] = ffma2(a13, w3f, acc1[o]);
        }
    }
    __syncthreads();
    #pragma unroll
    for (int g4 = 0; g4 < 4; g4++) {
        float4 s0, s1;
        const int ob = qt * 16 + 4 * g4;
        s0.x = fmaxf(acc0[4*g4  ].x + acc0[4*g4  ].y + cb0[ob  ], 0.f);
        s0.y = fmaxf(acc0[4*g4+1].x + acc0[4*g4+1].y + cb0[ob+1], 0.f);
        s0.z = fmaxf(acc0[4*g4+2].x + acc0[4*g4+2].y + cb0[ob+2], 0.f);
        s0.w = fmaxf(acc0[4*g4+3].x + acc0[4*g4+3].y + cb0[ob+3], 0.f);
        s1.x = fmaxf(acc1[4*g4  ].x + acc1[4*g4  ].y + cb0[ob  ], 0.f);
        s1.y = fmaxf(acc1[4*g4+1].x + acc1[4*g4+1].y + cb0[ob+1], 0.f);
        s1.z = fmaxf(acc1[4*g4+2].x + acc1[4*g4+2].y + cb0[ob+2], 0.f);
        s1.w = fmaxf(acc1[4*g4+3].x + acc1[4*g4+3].y + cb0[ob+3], 0.f);
        *(float4*)(r0 + ob) = s0;
        *(float4*)(r1 + ob) = s1;
    }
    __syncthreads();

    // ---------------- Layer 1: 64 -> 64, relu ----------------
    #pragma unroll
    for (int o = 0; o < 16; o++) { acc0[o] = make_float2(0.f,0.f); acc1[o] = make_float2(0.f,0.f); }
    #pragma unroll
    for (int c = 0; c < 8; c++) {
        const float4 qa0 = *(const float4*)(r0 + 8*c);
        const float4 qb0 = *(const float4*)(r0 + 8*c + 4);
        const float4 qa1 = *(const float4*)(r1 + 8*c);
        const float4 qb1 = *(const float4*)(r1 + 8*c + 4);
        const float2 a00 = make_float2(qa0.x,qa0.y), a01 = make_float2(qa0.z,qa0.w);
        const float2 a02 = make_float2(qb0.x,qb0.y), a03 = make_float2(qb0.z,qb0.w);
        const float2 a10 = make_float2(qa1.x,qa1.y), a11 = make_float2(qa1.z,qa1.w);
        const float2 a12 = make_float2(qb1.x,qb1.y), a13 = make_float2(qb1.z,qb1.w);
        #pragma unroll
        for (int o = 0; o < 16; o++) {
            const float4* wv = cw1 + (qt * 16 + o) * 16 + 2 * c;
            const float4 v0 = wv[0], v1 = wv[1];
            const float2 w0f = make_float2(v0.x,v0.y), w1f = make_float2(v0.z,v0.w);
            const float2 w2f = make_float2(v1.x,v1.y), w3f = make_float2(v1.z,v1.w);
            acc0[o] = ffma2(a00, w0f, acc0[o]); acc0[o] = ffma2(a01, w1f, acc0[o]);
            acc0[o] = ffma2(a02, w2f, acc0[o]); acc0[o] = ffma2(a03, w3f, acc0[o]);
            acc1[o] = ffma2(a10, w0f, acc1[o]); acc1[o] = ffma2(a11, w1f, acc1[o]);
            acc1[o] = ffma2(a12, w2f, acc1[o]); acc1[o] = ffma2(a13, w3f, acc1[o]);
        }
    }
    __syncthreads();
    #pragma unroll
    for (int g4 = 0; g4 < 4; g4++) {
        float4 s0, s1;
        const int ob = qt * 16 + 4 * g4;
        s0.x = fmaxf(acc0[4*g4  ].x + acc0[4*g4  ].y + cb1[ob  ], 0.f);
        s0.y = fmaxf(acc0[4*g4+1].x + acc0[4*g4+1].y + cb1[ob+1], 0.f);
        s0.z = fmaxf(acc0[4*g4+2].x + acc0[4*g4+2].y + cb1[ob+2], 0.f);
        s0.w = fmaxf(acc0[4*g4+3].x + acc0[4*g4+3].y + cb1[ob+3], 0.f);
        s1.x = fmaxf(acc1[4*g4  ].x + acc1[4*g4  ].y + cb1[ob  ], 0.f);
        s1.y = fmaxf(acc1[4*g4+1].x + acc1[4*g4+1].y + cb1[ob+1], 0.f);
        s1.z = fmaxf(acc1[4*g4+2].x + acc1[4*g4+2].y + cb1[ob+2], 0.f);
        s1.w = fmaxf(acc1[4*g4+3].x + acc1[4*g4+3].y + cb1[ob+3], 0.f);
        *(float4*)(r0 + ob) = s0;
        *(float4*)(r1 + ob) = s1;
    }
    __syncthreads();

    // ---------------- Layer 2: 64 -> 64, linear (base) ----------------
    #pragma unroll
    for (int o = 0; o < 16; o++) { acc0[o] = make_float2(0.f,0.f); acc1[o] = make_float2(0.f,0.f); }
    #pragma unroll
    for (int c = 0; c < 8; c++) {
        const float4 qa0 = *(const float4*)(r0 + 8*c);
        const float4 qb0 = *(const float4*)(r0 + 8*c + 4);
        const float4 qa1 = *(const float4*)(r1 + 8*c);
        const float4 qb1 = *(const float4*)(r1 + 8*c + 4);
        const float2 a00 = make_float2(qa0.x,qa0.y), a01 = make_float2(qa0.z,qa0.w);
        const float2 a02 = make_float2(qb0.x,qb0.y), a03 = make_float2(qb0.z,qb0.w);
        const float2 a10 = make_float2(qa1.x,qa1.y), a11 = make_float2(qa1.z,qa1.w);
        const float2 a12 = make_float2(qb1.x,qb1.y), a13 = make_float2(qb1.z,qb1.w);
        #pragma unroll
        for (int o = 0; o < 16; o++) {
            const float4* wv = cw2 + (qt * 16 + o) * 16 + 2 * c;
            const float4 v0 = wv[0], v1 = wv[1];
            const float2 w0f = make_float2(v0.x,v0.y), w1f = make_float2(v0.z,v0.w);
            const float2 w2f = make_float2(v1.x,v1.y), w3f = make_float2(v1.z,v1.w);
            acc0[o] = ffma2(a00, w0f, acc0[o]); acc0[o] = ffma2(a01, w1f, acc0[o]);
            acc0[o] = ffma2(a02, w2f, acc0[o]); acc0[o] = ffma2(a03, w3f, acc0[o]);
            acc1[o] = ffma2(a10, w0f, acc1[o]); acc1[o] = ffma2(a11, w1f, acc1[o]);
            acc1[o] = ffma2(a12, w2f, acc1[o]); acc1[o] = ffma2(a13, w3f, acc1[o]);
        }
    }
    __syncthreads();
    #pragma unroll
    for (int g4 = 0; g4 < 4; g4++) {
        float4 s0, s1;
        const int ob = qt * 16 + 4 * g4;
        s0.x = acc0[4*g4  ].x + acc0[4*g4  ].y + cb2[ob  ];
        s0.y = acc0[4*g4+1].x + acc0[4*g4+1].y + cb2[ob+1];
        s0.z = acc0[4*g4+2].x + acc0[4*g4+2].y + cb2[ob+2];
        s0.w = acc0[4*g4+3].x + acc0[4*g4+3].y + cb2[ob+3];
        s1.x = acc1[4*g4  ].x + acc1[4*g4  ].y + cb2[ob  ];
        s1.y = acc1[4*g4+1].x + acc1[4*g4+1].y + cb2[ob+1];
        s1.z = acc1[4*g4+2].x + acc1[4*g4+2].y + cb2[ob+2];
        s1.w = acc1[4*g4+3].x + acc1[4*g4+3].y + cb2[ob+3];
        *(float4*)(r0 + ob) = s0;
        *(float4*)(r1 + ob) = s1;
    }
    __syncthreads();
    // row[0..63] = bp, row[64..91] = dvec

    // ---------------- RGB head: 8 outputs per warp-quarter, 2 points --------
    float h80[8], h81[8];
    #pragma unroll
    for (int o = 0; o < 8; o++) {
        const int og = qt * 8 + o;
        h80[o] = cbr[og]; h81[o] = cbr[og];
    }
    #pragma unroll
    for (int c = 0; c < 7; c++) {
        const float4 d0 = *(const float4*)(r0 + 64 + 4*c);
        const float4 d1 = *(const float4*)(r1 + 64 + 4*c);
        #pragma unroll
        for (int o = 0; o < 8; o++) {
            const float4 v = cwrd[(qt * 8 + o) * 7 + c];
            h80[o] = fmaf(d0.x, v.x, fmaf(d0.y, v.y, fmaf(d0.z, v.z, fmaf(d0.w, v.w, h80[o]))));
            h81[o] = fmaf(d1.x, v.x, fmaf(d1.y, v.y, fmaf(d1.z, v.z, fmaf(d1.w, v.w, h81[o]))));
        }
    }
    {
        float2 hb0[8], hb1[8];
        #pragma unroll
        for (int o = 0; o < 8; o++) { hb0[o] = make_float2(0.f,0.f); hb1[o] = make_float2(0.f,0.f); }
        #pragma unroll
        for (int c = 0; c < 8; c++) {
            const float4 qa0 = *(const float4*)(r0 + 8*c);
            const float4 qb0 = *(const float4*)(r0 + 8*c + 4);
            const float4 qa1 = *(const float4*)(r1 + 8*c);
            const float4 qb1 = *(const float4*)(r1 + 8*c + 4);
            const float2 a00 = make_float2(qa0.x,qa0.y), a01 = make_float2(qa0.z,qa0.w);
            const float2 a02 = make_float2(qb0.x,qb0.y), a03 = make_float2(qb0.z,qb0.w);
            const float2 a10 = make_float2(qa1.x,qa1.y), a11 = make_float2(qa1.z,qa1.w);
            const float2 a12 = make_float2(qb1.x,qb1.y), a13 = make_float2(qb1.z,qb1.w);
            #pragma unroll
            for (int o = 0; o < 8; o++) {
                const float4* wv = cwrb + (qt * 8 + o) * 16 + 2 * c;
                const float4 v0 = wv[0], v1 = wv[1];
                const float2 w0f = make_float2(v0.x,v0.y), w1f = make_float2(v0.z,v0.w);
                const float2 w2f = make_float2(v1.x,v1.y), w3f = make_float2(v1.z,v1.w);
                hb0[o] = ffma2(a00, w0f, hb0[o]); hb0[o] = ffma2(a01, w1f, hb0[o]);
                hb0[o] = ffma2(a02, w2f, hb0[o]); hb0[o] = ffma2(a03, w3f, hb0[o]);
                hb1[o] = ffma2(a10, w0f, hb1[o]); hb1[o] = ffma2(a11, w1f, hb1[o]);
                hb1[o] = ffma2(a12, w2f, hb1[o]); hb1[o] = ffma2(a13, w3f, hb1[o]);
            }
        }
        #pragma unroll
        for (int o = 0; o < 8; o++) {
            h80[o] += hb0[o].x + hb0[o].y;
            h81[o] += hb1[o].x + hb1[o].y;
        }
    }
    __syncthreads();
    {
        float4 s0, s1, s2, s3;
        s0.x = h80[0]; s0.y = h80[1]; s0.z = h80[2]; s0.w = h80[3];
        s1.x = h80[4]; s1.y = h80[5]; s1.z = h80[6]; s1.w = h80[7];
        s2.x = h81[0]; s2.y = h81[1]; s2.z = h81[2]; s2.w = h81[3];
        s3.x = h81[4]; s3.y = h81[5]; s3.z = h81[6]; s3.w = h81[7];
        *(float4*)(r0 + 64 + qt * 8)     = s0;
        *(float4*)(r0 + 64 + qt * 8 + 4) = s1;
        *(float4*)(r1 + 64 + qt * 8)     = s2;
        *(float4*)(r1 + 64 + qt * 8 + 4) = s3;
    }
    __syncthreads();

    if (qt == 0) {
        #pragma unroll
        for (int s = 0; s < 2; s++) {
            float* r = s ? r1 : r0;
            const int ii = ib + (s ? p1 : p0);
            float rg[32];
            #pragma unroll
            for (int q = 0; q < 8; q++) {
                const float4 v = *(const float4*)(r + 64 + 4*q);
                rg[4*q] = v.x; rg[4*q+1] = v.y; rg[4*q+2] = v.z; rg[4*q+3] = v.w;
            }
            #pragma unroll
            for (int c = 0; c < 3; c++) {
                float a = cbc[c];
                const float4* wcrow = cwc + c * 8;
                #pragma unroll
                for (int q = 0; q < 8; q++) {
                    const float4 v = wcrow[q];
                    a = fmaf(rg[4*q],   v.x, a);
                    a = fmaf(rg[4*q+1], v.y, a);
                    a = fmaf(rg[4*q+2], v.z, a);
                    a = fmaf(rg[4*q+3], v.w, a);
                }
                out[4 * ii + c] = 1.f / (1.f + expf(-a));
            }
        }
    } else if (qt == 1) {
        #pragma unroll
        for (int s = 0; s < 2; s++) {
            float* r = s ? r1 : r0;
            const int ii = ib + (s ? p1 : p0);
            float2 a2 = make_float2(0.f, 0.f);
            #pragma unroll
            for (int q = 0; q < 16; q++) {
                const float4 v = cwd[q];
                const float4 aq = *(const float4*)(r + 4*q);
                a2 = ffma2(make_float2(aq.x, aq.y), make_float2(v.x, v.y), a2);
                a2 = ffma2(make_float2(aq.z, aq.w), make_float2(v.z, v.w), a2);
            }
            const float xd = a2.x + a2.y + cbd[0];
            out[4 * ii + 3] = fmaxf(xd, 0.f) + log1pf(expf(-fabsf(xd)));
        }
    }
}

extern "C" void kernel_launch(void* const* d_in, const int* in_sizes, int n_in,
                              void* d_out, int out_size) {
    (void)in_sizes; (void)n_in; (void)out_size;
    const float*  pos = (const float*)d_in[0];
    const float*  dir = (const float*)d_in[1];
    const float2* tab = (const float2*)d_in[2];
    const float *w0 = (const float*)d_in[3],  *b0 = (const float*)d_in[4];
    const float *w1 = (const float*)d_in[5],  *b1 = (const float*)d_in[6];
    const float *w2 = (const float*)d_in[7],  *b2 = (const float*)d_in[8];
    const float *wr = (const float*)d_in[9],  *br = (const float*)d_in[10];
    const float *wc = (const float*)d_in[11], *bc = (const float*)d_in[12];
    const float *wd = (const float*)d_in[13], *bd = (const float*)d_in[14];
    float* out = (float*)d_out;

    // 1) Repack weights into device scratch (packed layout)
    repack_kernel<<<1, 256>>>(w0, b0, w1, b1, w2, b2, wr, br, wc, bc, wd, bd);

    // 2) Device-to-device copy into the constant bank (graph-capturable memcpy node)
    void* g_ptr = nullptr;
    cudaGetSymbolAddress(&g_ptr, g_wpack);
    cudaMemcpyToSymbolAsync(c_wpack, g_ptr, W_FLOATS * sizeof(float), 0,
                            cudaMemcpyDeviceToDevice, 0);

    // 3) Hash-grid encode (independent of weights)
    encode_kernel<<<(16 * N_PTS) / 256, 256>>>(pos, tab);

    // 4) MLP + heads
    cudaFuncSetAttribute(mlp_kernel,
                         cudaFuncAttributeMaxDynamicSharedMemorySize, SMEM_BYTES);
    mlp_kernel<<<N_PTS / PPB, BLOCK, SMEM_BYTES>>>(dir, out);
}

// round 11
// speedup vs baseline: 7.3249x; 7.3249x over previous
#include <cuda_runtime.h>
#include <mma.h>

using namespace nvcuda;

#define N_PTS   524288            // = 1 << 19
#define PT_BITS 19
#define TBITS   19
#define TMASK   ((1u << TBITS) - 1u)
#define BLOCK   256
#define PPB     128
#define LDA     68                // act buffer stride (floats): mult of 4 (16B rows)
#define LDD     36                // dvec buffer stride
// smem: bufA[128*68] + bufB[128*68] + dv[128*36] + brep[16*68]
#define SMEM_FLOATS (2 * 128 * LDA + 128 * LDD + 16 * LDA)
#define SMEM_BYTES  (SMEM_FLOATS * 4)

// Feature-major hash-encode scratch: g_enc[f * N_PTS + pt], f in [0,32)
__device__ float g_enc[32u * N_PTS];

// Packed dual-FMA on float2 (sm_103a f32x2 pipe) — encode kernel only
__device__ __forceinline__ float2 ffma2(float2 a, float2 b, float2 c) {
    float2 d;
    asm("fma.rn.f32x2 %0, %1, %2, %3;"
        : "=l"(reinterpret_cast<unsigned long long&>(d))
        : "l"(reinterpret_cast<unsigned long long&>(a)),
          "l"(reinterpret_cast<unsigned long long&>(b)),
          "l"(reinterpret_cast<unsigned long long&>(c)));
    return d;
}

__constant__ float c_scale[16] = {
    16.f, 21.f, 27.f, 36.f, 48.f, 64.f, 84.f, 111.f,
    147.f, 194.f, 256.f, 337.f, 445.f, 588.f, 776.f, 1024.f
};

// ===================== Kernel A: hash-grid encode (unchanged) =====================
__global__ __launch_bounds__(256) void encode_kernel(
    const float* __restrict__ pos, const float2* __restrict__ tab)
{
    const unsigned g  = blockIdx.x * 256u + threadIdx.x;
    const int      l  = (int)(g >> PT_BITS);
    const unsigned pt = g & (N_PTS - 1u);

    const float px = pos[3 * pt], py = pos[3 * pt + 1], pz = pos[3 * pt + 2];
    const float sc = c_scale[l];
    const float sx = px * sc, sy = py * sc, sz = pz * sc;
    const float fx = floorf(sx), fy = floorf(sy), fz = floorf(sz);
    const float ox = sx - fx, oy = sy - fy, oz = sz - fz;
    const unsigned hx0 = (unsigned)(int)fx;                 // x prime = 1
    const unsigned hx1 = (unsigned)(int)ceilf(sx);
    const unsigned hy0 = (unsigned)(int)fy * 2654435761u;
    const unsigned hy1 = (unsigned)(int)ceilf(sy) * 2654435761u;
    const unsigned hz0 = (unsigned)(int)fz * 805459861u;
    const unsigned hz1 = (unsigned)(int)ceilf(sz) * 805459861u;
    const unsigned lvl = ((unsigned)l) << TBITS;
    const float wx0 = 1.f - ox, wy0 = 1.f - oy, wz0 = 1.f - oz;

    float2 a = make_float2(0.f, 0.f);
    #pragma unroll
    for (int p = 0; p < 4; p++) {
        const unsigned hyz = ((p & 1) ? hy1 : hy0) ^ ((p & 2) ? hz1 : hz0);
        const unsigned i0 = (hx0 ^ hyz) & TMASK;
        const unsigned i1 = (hx1 ^ hyz) & TMASK;
        const float4 q = __ldg((const float4*)(tab + ((i0 & ~1u) + lvl)));
        const float2 lo = make_float2(q.x, q.y);
        const float2 hi = make_float2(q.z, q.w);
        float2 e0 = (i0 & 1u) ? hi : lo;
        float2 e1;
        if (i1 == (i0 ^ 1u)) {
            e1 = (i0 & 1u) ? lo : hi;
        } else {
            e1 = __ldg(&tab[i1 + lvl]);
        }
        const float wyz = ((p & 1) ? oy : wy0) * ((p & 2) ? oz : wz0);
        const float w0f = wx0 * wyz, w1f = ox * wyz;
        a = ffma2(make_float2(w0f, w0f), e0, a);
        a = ffma2(make_float2(w1f, w1f), e1, a);
    }
    g_enc[(2u * l)     * (unsigned)N_PTS + pt] = a.x;
    g_enc[(2u * l + 1) * (unsigned)N_PTS + pt] = a.y;
}

// ---- split-tf32 fragment conversion: raw floats -> (hi, lo) tf32 fragments ----
template <typename Frag>
__device__ __forceinline__ void split_tf32(Frag& hi, Frag& lo) {
    #pragma unroll
    for (int e = 0; e < hi.num_elements; e++) {
        const float x = hi.x[e];
        const float h = wmma::__float_to_tf32(x);
        hi.x[e] = h;
        lo.x[e] = wmma::__float_to_tf32(x - h);
    }
}

// One 128xK @ KxN=64 layer: 8 warps = 4 n-slices x 2 m-halves (4 m-tiles each).
template <int NK, bool RELU>
__device__ __forceinline__ void wmma_layer64(
    const float* Asm, const float* __restrict__ Bg,
    float* Csm, const float* brep, int w)
{
    const int n0 = (w & 3) * 16;
    const int mb = (w >> 2) * 4;          // first of 4 m-tiles
    wmma::fragment<wmma::accumulator, 16, 16, 8, float> acc[4];
    #pragma unroll
    for (int i = 0; i < 4; i++)
        wmma::load_matrix_sync(acc[i], brep + n0, LDA, wmma::mem_row_major);

    #pragma unroll
    for (int k = 0; k < NK; k += 8) {
        wmma::fragment<wmma::matrix_b, 16, 16, 8, wmma::precision::tf32, wmma::row_major> bh, bl;
        wmma::load_matrix_sync(bh, Bg + k * 64 + n0, 64);
        split_tf32(bh, bl);
        #pragma unroll
        for (int i = 0; i < 4; i++) {
            wmma::fragment<wmma::matrix_a, 16, 16, 8, wmma::precision::tf32, wmma::row_major> ah, al;
            wmma::load_matrix_sync(ah, Asm + (mb + i) * 16 * LDA + k, LDA);
            split_tf32(ah, al);
            wmma::mma_sync(acc[i], ah, bh, acc[i]);
            wmma::mma_sync(acc[i], al, bh, acc[i]);
            wmma::mma_sync(acc[i], ah, bl, acc[i]);
        }
    }
    #pragma unroll
    for (int i = 0; i < 4; i++) {
        if (RELU) {
            #pragma unroll
            for (int e = 0; e < acc[i].num_elements; e++)
                acc[i].x[e] = fmaxf(acc[i].x[e], 0.f);
        }
        wmma::store_matrix_sync(Csm + (mb + i) * 16 * LDA + n0, acc[i], LDA, wmma::mem_row_major);
    }
}

// RGB head: rgbh[128][32] = dvec[128][32pad] @ wr[0:32] + bp[128][64] @ wr[27:91]
__device__ __forceinline__ void wmma_head(
    const float* bp, const float* dv, const float* __restrict__ wrg,
    float* Csm, const float* brep, int w)
{
    const int n0 = (w & 1) * 16;
    const int mb = (w >> 1) * 2;          // first of 2 m-tiles
    wmma::fragment<wmma::accumulator, 16, 16, 8, float> acc[2];
    #pragma unroll
    for (int i = 0; i < 2; i++)
        wmma::load_matrix_sync(acc[i], brep + n0, LDA, wmma::mem_row_major);

    #pragma unroll
    for (int k = 0; k < 64; k += 8) {     // base part: B = wr rows 27..90
        wmma::fragment<wmma::matrix_b, 16, 16, 8, wmma::precision::tf32, wmma::row_major> bh, bl;
        wmma::load_matrix_sync(bh, wrg + (27 + k) * 32 + n0, 32);
        split_tf32(bh, bl);
        #pragma unroll
        for (int i = 0; i < 2; i++) {
            wmma::fragment<wmma::matrix_a, 16, 16, 8, wmma::precision::tf32, wmma::row_major> ah, al;
            wmma::load_matrix_sync(ah, bp + (mb + i) * 16 * LDA + k, LDA);
            split_tf32(ah, al);
            wmma::mma_sync(acc[i], ah, bh, acc[i]);
            wmma::mma_sync(acc[i], al, bh, acc[i]);
            wmma::mma_sync(acc[i], ah, bl, acc[i]);
        }
    }
    #pragma unroll
    for (int k = 0; k < 32; k += 8) {     // dir part: B = wr rows 0..31 (dv cols 27..31 = 0)
        wmma::fragment<wmma::matrix_b, 16, 16, 8, wmma::precision::tf32, wmma::row_major> bh, bl;
        wmma::load_matrix_sync(bh, wrg + k * 32 + n0, 32);
        split_tf32(bh, bl);
        #pragma unroll
        for (int i = 0; i < 2; i++) {
            wmma::fragment<wmma::matrix_a, 16, 16, 8, wmma::precision::tf32, wmma::row_major> ah, al;
            wmma::load_matrix_sync(ah, dv + (mb + i) * 16 * LDD + k, LDD);
            split_tf32(ah, al);
            wmma::mma_sync(acc[i], ah, bh, acc[i]);
            wmma::mma_sync(acc[i], al, bh, acc[i]);
            wmma::mma_sync(acc[i], ah, bl, acc[i]);
        }
    }
    #pragma unroll
    for (int i = 0; i < 2; i++)
        wmma::store_matrix_sync(Csm + (mb + i) * 16 * LDA + n0, acc[i], LDA, wmma::mem_row_major);
}

// ===================== Kernel B: MLP + heads (wmma tf32-split) =====================
__global__ __launch_bounds__(BLOCK, 2) void mlp_kernel(
    const float* __restrict__ dir,
    const float* __restrict__ w0, const float* __restrict__ b0,
    const float* __restrict__ w1, const float* __restrict__ b1,
    const float* __restrict__ w2, const float* __restrict__ b2,
    const float* __restrict__ wr, const float* __restrict__ br,
    const float* __restrict__ wc, const float* __restrict__ bc,
    const float* __restrict__ wd, const float* __restrict__ bd,
    float* __restrict__ out)
{
    extern __shared__ float sm[];
    float* bufA = sm;                               // [128][68]
    float* bufB = sm + 128 * LDA;                   // [128][68]
    float* dv   = sm + 2 * 128 * LDA;               // [128][36]
    float* brep = sm + 2 * 128 * LDA + 128 * LDD;   // [16][68]

    const int t  = threadIdx.x;
    const int w  = t >> 5;
    const int ib = blockIdx.x * PPB;

    // ---- Stage enc: coalesced LDG x4 -> STS.128 into bufA[pt][0..31] ----
    for (int k = t; k < 8 * PPB; k += BLOCK) {
        const int fg = k >> 7;
        const int p  = k & (PPB - 1);
        const unsigned gp = (unsigned)(ib + p);
        const int f = 4 * fg;
        float4 v;
        v.x = g_enc[(unsigned)(f    ) * N_PTS + gp];
        v.y = g_enc[(unsigned)(f + 1) * N_PTS + gp];
        v.z = g_enc[(unsigned)(f + 2) * N_PTS + gp];
        v.w = g_enc[(unsigned)(f + 3) * N_PTS + gp];
        *(float4*)(bufA + p * LDA + f) = v;
    }

    // ---- Direction encode: 2 threads per point -> dv[pt][0..31] (27..31 zero) ----
    {
        const int pt = t & (PPB - 1);
        const int hf = t >> 7;
        const int i  = ib + pt;
        float* row = dv + pt * LDD;
        const float fr[4] = {1.f, 2.5198421f, 6.3496042f, 16.f};
        if (hf == 0) {
            const float dx = dir[3 * i], dy = dir[3 * i + 1];
            const float tx = 6.2831855f * dx, ty = 6.2831855f * dy;
            #pragma unroll
            for (int k = 0; k < 4; k++) {
                float s, c;
                sincosf(tx * fr[k], &s, &c);
                row[k] = s; row[12 + k] = c;
                sincosf(ty * fr[k], &s, &c);
                row[4 + k] = s; row[16 + k] = c;
            }
        } else {
            const float dx = dir[3 * i], dy = dir[3 * i + 1], dz = dir[3 * i + 2];
            const float tz = 6.2831855f * dz;
            #pragma unroll
            for (int k = 0; k < 4; k++) {
                float s, c;
                sincosf(tz * fr[k], &s, &c);
                row[8 + k] = s; row[20 + k] = c;
            }
            row[24] = dx; row[25] = dy; row[26] = dz;
            row[27] = 0.f; row[28] = 0.f; row[29] = 0.f; row[30] = 0.f; row[31] = 0.f;
        }
    }
    // ---- bias_rep <- b0 ----
    for (int k = t; k < 16 * 64; k += BLOCK)
        brep[(k >> 6) * LDA + (k & 63)] = b0[k & 63];
    __syncthreads();

    // ---- Layer 0: [128x32] @ w0[32x64] + b0, relu -> bufB ----
    wmma_layer64<32, true>(bufA, w0, bufB, brep, w);
    __syncthreads();
    for (int k = t; k < 16 * 64; k += BLOCK)
        brep[(k >> 6) * LDA + (k & 63)] = b1[k & 63];
    __syncthreads();

    // ---- Layer 1: [128x64] @ w1 + b1, relu -> bufA ----
    wmma_layer64<64, true>(bufB, w1, bufA, brep, w);
    __syncthreads();
    for (int k = t; k < 16 * 64; k += BLOCK)
        brep[(k >> 6) * LDA + (k & 63)] = b2[k & 63];
    __syncthreads();

    // ---- Layer 2: [128x64] @ w2 + b2, linear -> bufB (= bp) ----
    wmma_layer64<64, false>(bufA, w2, bufB, brep, w);
    __syncthreads();
    for (int k = t; k < 16 * 32; k += BLOCK)
        brep[(k >> 5) * LDA + (k & 31)] = br[k & 31];
    __syncthreads();

    // ---- RGB head matrix: rgbh -> bufA[pt][0..31] ----
    wmma_head(bufB, dv, wr, bufA, brep, w);
    __syncthreads();

    // ---- Tail: t<128 -> rgb, t>=128 -> density ----
    if (t < PPB) {
        const int pt = t;
        const int ii = ib + pt;
        const float* r = bufA + pt * LDA;
        float a0 = __ldg(&bc[0]), a1 = __ldg(&bc[1]), a2 = __ldg(&bc[2]);
        #pragma unroll
        for (int q = 0; q < 8; q++) {
            const float4 v = *(const float4*)(r + 4 * q);
            #pragma unroll
            for (int j = 0; j < 4; j++) {
                const float x = (&v.x)[j];
                const int kk = 4 * q + j;
                a0 = fmaf(x, __ldg(&wc[kk * 3 + 0]), a0);
                a1 = fmaf(x, __ldg(&wc[kk * 3 + 1]), a1);
                a2 = fmaf(x, __ldg(&wc[kk * 3 + 2]), a2);
            }
        }
        out[4 * ii + 0] = 1.f / (1.f + expf(-a0));
        out[4 * ii + 1] = 1.f / (1.f + expf(-a1));
        out[4 * ii + 2] = 1.f / (1.f + expf(-a2));
    } else {
        const int pt = t - PPB;
        const int ii = ib + pt;
        const float* r = bufB + pt * LDA;
        float a = __ldg(&bd[0]);
        #pragma unroll
        for (int q = 0; q < 16; q++) {
            const float4 v = *(const float4*)(r + 4 * q);
            a = fmaf(v.x, __ldg(&wd[4 * q + 0]), a);
            a = fmaf(v.y, __ldg(&wd[4 * q + 1]), a);
            a = fmaf(v.z, __ldg(&wd[4 * q + 2]), a);
            a = fmaf(v.w, __ldg(&wd[4 * q + 3]), a);
        }
        out[4 * ii + 3] = fmaxf(a, 0.f) + log1pf(expf(-fabsf(a)));
    }
}

extern "C" void kernel_launch(void* const* d_in, const int* in_sizes, int n_in,
                              void* d_out, int out_size) {
    (void)in_sizes; (void)n_in; (void)out_size;
    const float*  pos = (const float*)d_in[0];
    const float*  dir = (const float*)d_in[1];
    const float2* tab = (const float2*)d_in[2];
    const float *w0 = (const float*)d_in[3],  *b0 = (const float*)d_in[4];
    const float *w1 = (const float*)d_in[5],  *b1 = (const float*)d_in[6];
    const float *w2 = (const float*)d_in[7],  *b2 = (const float*)d_in[8];
    const float *wr = (const float*)d_in[9],  *br = (const float*)d_in[10];
    const float *wc = (const float*)d_in[11], *bc = (const float*)d_in[12];
    const float *wd = (const float*)d_in[13], *bd = (const float*)d_in[14];
    float* out = (float*)d_out;

    encode_kernel<<<(16 * N_PTS) / 256, 256>>>(pos, tab);

    cudaFuncSetAttribute(mlp_kernel,
                         cudaFuncAttributeMaxDynamicSharedMemorySize, SMEM_BYTES);
    mlp_kernel<<<N_PTS / PPB, BLOCK, SMEM_BYTES>>>(
        dir, w0, b0, w1, b1, w2, b2, wr, br, wc, bc, wd, bd, out);
}

// round 12
// speedup vs baseline: 10.3621x; 1.4146x over previous
#include <cuda_runtime.h>
#include <cuda_bf16.h>
#include <mma.h>

using namespace nvcuda;

#define N_PTS   524288            // = 1 << 19
#define PT_BITS 19
#define TBITS   19
#define TMASK   ((1u << TBITS) - 1u)
#define BLOCK   256
#define PPB     128
#define LDF     68                // fp32 buf stride (floats)
#define LDAB    72                // bf16 act stride (elems), 144B (mult of 16B)
#define LDDV    40                // bf16 dvec stride (elems), 80B
// smem bytes: bufF + actH + actL + dvH + dvL + brep
#define OFF_BUFF 0
#define OFF_ACTH 34816
#define OFF_ACTL 53248
#define OFF_DVH  71680
#define OFF_DVL  81920
#define OFF_BREP 92160
#define SMEM_BYTES 96512

// Feature-major hash-encode scratch
__device__ float g_enc[32u * N_PTS];
// Pre-split bf16 weights (hi/lo), B-matrix layout [K][N] row-major
__device__ __align__(16) __nv_bfloat16 g_w0h[32 * 64], g_w0l[32 * 64];
__device__ __align__(16) __nv_bfloat16 g_w1h[64 * 64], g_w1l[64 * 64];
__device__ __align__(16) __nv_bfloat16 g_w2h[64 * 64], g_w2l[64 * 64];
__device__ __align__(16) __nv_bfloat16 g_wrh[91 * 32], g_wrl[91 * 32];

__device__ __forceinline__ float2 ffma2(float2 a, float2 b, float2 c) {
    float2 d;
    asm("fma.rn.f32x2 %0, %1, %2, %3;"
        : "=l"(reinterpret_cast<unsigned long long&>(d))
        : "l"(reinterpret_cast<unsigned long long&>(a)),
          "l"(reinterpret_cast<unsigned long long&>(b)),
          "l"(reinterpret_cast<unsigned long long&>(c)));
    return d;
}

__constant__ float c_scale[16] = {
    16.f, 21.f, 27.f, 36.f, 48.f, 64.f, 84.f, 111.f,
    147.f, 194.f, 256.f, 337.f, 445.f, 588.f, 776.f, 1024.f
};

__device__ __forceinline__ void split1(float x, __nv_bfloat16& h, __nv_bfloat16& l) {
    h = __float2bfloat16_rn(x);
    l = __float2bfloat16_rn(x - __bfloat162float(h));
}

// Split a float4 into 4 hi + 4 lo bf16, stored as one 8B write each.
__device__ __forceinline__ void split4_store(float4 v, __nv_bfloat16* ph, __nv_bfloat16* pl) {
    __nv_bfloat16 h[4], l[4];
    split1(v.x, h[0], l[0]); split1(v.y, h[1], l[1]);
    split1(v.z, h[2], l[2]); split1(v.w, h[3], l[3]);
    *(uint2*)ph = *(uint2*)h;
    *(uint2*)pl = *(uint2*)l;
}

// ===================== Kernel 0: pre-split weights to bf16 hi/lo =====================
__global__ __launch_bounds__(256) void split_kernel(
    const float* __restrict__ w0, const float* __restrict__ w1,
    const float* __restrict__ w2, const float* __restrict__ wr)
{
    const int t = blockIdx.x * 256 + threadIdx.x;
    for (int k = t; k < 32 * 64; k += gridDim.x * 256) split1(w0[k], g_w0h[k], g_w0l[k]);
    for (int k = t; k < 64 * 64; k += gridDim.x * 256) {
        split1(w1[k], g_w1h[k], g_w1l[k]);
        split1(w2[k], g_w2h[k], g_w2l[k]);
    }
    for (int k = t; k < 91 * 32; k += gridDim.x * 256) split1(wr[k], g_wrh[k], g_wrl[k]);
}

// ===================== Kernel A: hash-grid encode (unchanged) =====================
__global__ __launch_bounds__(256) void encode_kernel(
    const float* __restrict__ pos, const float2* __restrict__ tab)
{
    const unsigned g  = blockIdx.x * 256u + threadIdx.x;
    const int      l  = (int)(g >> PT_BITS);
    const unsigned pt = g & (N_PTS - 1u);

    const float px = pos[3 * pt], py = pos[3 * pt + 1], pz = pos[3 * pt + 2];
    const float sc = c_scale[l];
    const float sx = px * sc, sy = py * sc, sz = pz * sc;
    const float fx = floorf(sx), fy = floorf(sy), fz = floorf(sz);
    const float ox = sx - fx, oy = sy - fy, oz = sz - fz;
    const unsigned hx0 = (unsigned)(int)fx;                 // x prime = 1
    const unsigned hx1 = (unsigned)(int)ceilf(sx);
    const unsigned hy0 = (unsigned)(int)fy * 2654435761u;
    const unsigned hy1 = (unsigned)(int)ceilf(sy) * 2654435761u;
    const unsigned hz0 = (unsigned)(int)fz * 805459861u;
    const unsigned hz1 = (unsigned)(int)ceilf(sz) * 805459861u;
    const unsigned lvl = ((unsigned)l) << TBITS;
    const float wx0 = 1.f - ox, wy0 = 1.f - oy, wz0 = 1.f - oz;

    float2 a = make_float2(0.f, 0.f);
    #pragma unroll
    for (int p = 0; p < 4; p++) {
        const unsigned hyz = ((p & 1) ? hy1 : hy0) ^ ((p & 2) ? hz1 : hz0);
        const unsigned i0 = (hx0 ^ hyz) & TMASK;
        const unsigned i1 = (hx1 ^ hyz) & TMASK;
        const float4 q = __ldg((const float4*)(tab + ((i0 & ~1u) + lvl)));
        const float2 lo = make_float2(q.x, q.y);
        const float2 hi = make_float2(q.z, q.w);
        float2 e0 = (i0 & 1u) ? hi : lo;
        float2 e1;
        if (i1 == (i0 ^ 1u)) {
            e1 = (i0 & 1u) ? lo : hi;
        } else {
            e1 = __ldg(&tab[i1 + lvl]);
        }
        const float wyz = ((p & 1) ? oy : wy0) * ((p & 2) ? oz : wz0);
        const float w0f = wx0 * wyz, w1f = ox * wyz;
        a = ffma2(make_float2(w0f, w0f), e0, a);
        a = ffma2(make_float2(w1f, w1f), e1, a);
    }
    g_enc[(2u * l)     * (unsigned)N_PTS + pt] = a.x;
    g_enc[(2u * l + 1) * (unsigned)N_PTS + pt] = a.y;
}

// One [128xK] @ [Kx64] layer; 8 warps = 4 n-slices x 2 m-halves (4 m-tiles each).
// 3-term bf16 split MMA: ah*bh + al*bh + ah*bl.
template <int NK, bool RELU>
__device__ __forceinline__ void bf16_layer64(
    const __nv_bfloat16* Ah, const __nv_bfloat16* Al,
    const __nv_bfloat16* __restrict__ Bh, const __nv_bfloat16* __restrict__ Bl,
    float* Csm, const float* brep, int w)
{
    const int n0 = (w & 3) * 16;
    const int mb = (w >> 2) * 4;
    wmma::fragment<wmma::accumulator, 16, 16, 16, float> acc[4];
    #pragma unroll
    for (int i = 0; i < 4; i++)
        wmma::load_matrix_sync(acc[i], brep + n0, LDF, wmma::mem_row_major);

    #pragma unroll
    for (int k = 0; k < NK; k += 16) {
        wmma::fragment<wmma::matrix_b, 16, 16, 16, __nv_bfloat16, wmma::row_major> bh, bl;
        wmma::load_matrix_sync(bh, Bh + k * 64 + n0, 64);
        wmma::load_matrix_sync(bl, Bl + k * 64 + n0, 64);
        #pragma unroll
        for (int i = 0; i < 4; i++) {
            wmma::fragment<wmma::matrix_a, 16, 16, 16, __nv_bfloat16, wmma::row_major> ah, al;
            wmma::load_matrix_sync(ah, Ah + (mb + i) * 16 * LDAB + k, LDAB);
            wmma::load_matrix_sync(al, Al + (mb + i) * 16 * LDAB + k, LDAB);
            wmma::mma_sync(acc[i], ah, bh, acc[i]);
            wmma::mma_sync(acc[i], al, bh, acc[i]);
            wmma::mma_sync(acc[i], ah, bl, acc[i]);
        }
    }
    #pragma unroll
    for (int i = 0; i < 4; i++) {
        if (RELU) {
            #pragma unroll
            for (int e = 0; e < acc[i].num_elements; e++)
                acc[i].x[e] = fmaxf(acc[i].x[e], 0.f);
        }
        wmma::store_matrix_sync(Csm + (mb + i) * 16 * LDF + n0, acc[i], LDF, wmma::mem_row_major);
    }
}

// RGB head: rgbh[128][32] = dv[128][32] @ wr[0:32] + bp[128][64] @ wr[27:91]
__device__ __forceinline__ void bf16_head(
    const __nv_bfloat16* bpH, const __nv_bfloat16* bpL,
    const __nv_bfloat16* dvH, const __nv_bfloat16* dvL,
    float* Csm, const float* brep, int w)
{
    const int n0 = (w & 1) * 16;
    const int mb = (w >> 1) * 2;
    wmma::fragment<wmma::accumulator, 16, 16, 16, float> acc[2];
    #pragma unroll
    for (int i = 0; i < 2; i++)
        wmma::load_matrix_sync(acc[i], brep + n0, LDF, wmma::mem_row_major);

    #pragma unroll
    for (int k = 0; k < 64; k += 16) {     // base part: wr rows 27..90
        wmma::fragment<wmma::matrix_b, 16, 16, 16, __nv_bfloat16, wmma::row_major> bh, bl;
        wmma::load_matrix_sync(bh, g_wrh + (27 + k) * 32 + n0, 32);
        wmma::load_matrix_sync(bl, g_wrl + (27 + k) * 32 + n0, 32);
        #pragma unroll
        for (int i = 0; i < 2; i++) {
            wmma::fragment<wmma::matrix_a, 16, 16, 16, __nv_bfloat16, wmma::row_major> ah, al;
            wmma::load_matrix_sync(ah, bpH + (mb + i) * 16 * LDAB + k, LDAB);
            wmma::load_matrix_sync(al, bpL + (mb + i) * 16 * LDAB + k, LDAB);
            wmma::mma_sync(acc[i], ah, bh, acc[i]);
            wmma::mma_sync(acc[i], al, bh, acc[i]);
            wmma::mma_sync(acc[i], ah, bl, acc[i]);
        }
    }
    #pragma unroll
    for (int k = 0; k < 32; k += 16) {     // dir part: wr rows 0..31 (dv cols 27..31 = 0)
        wmma::fragment<wmma::matrix_b, 16, 16, 16, __nv_bfloat16, wmma::row_major> bh, bl;
        wmma::load_matrix_sync(bh, g_wrh + k * 32 + n0, 32);
        wmma::load_matrix_sync(bl, g_wrl + k * 32 + n0, 32);
        #pragma unroll
        for (int i = 0; i < 2; i++) {
            wmma::fragment<wmma::matrix_a, 16, 16, 16, __nv_bfloat16, wmma::row_major> ah, al;
            wmma::load_matrix_sync(ah, dvH + (mb + i) * 16 * LDDV + k, LDDV);
            wmma::load_matrix_sync(al, dvL + (mb + i) * 16 * LDDV + k, LDDV);
            wmma::mma_sync(acc[i], ah, bh, acc[i]);
            wmma::mma_sync(acc[i], al, bh, acc[i]);
            wmma::mma_sync(acc[i], ah, bl, acc[i]);
        }
    }
    #pragma unroll
    for (int i = 0; i < 2; i++)
        wmma::store_matrix_sync(Csm + (mb + i) * 16 * LDF + n0, acc[i], LDF, wmma::mem_row_major);
}

// ===================== Kernel B: MLP + heads (bf16-split wmma) =====================
__global__ __launch_bounds__(BLOCK, 2) void mlp_kernel(
    const float* __restrict__ dir,
    const float* __restrict__ b0, const float* __restrict__ b1,
    const float* __restrict__ b2, const float* __restrict__ br,
    const float* __restrict__ wc, const float* __restrict__ bc,
    const float* __restrict__ wd, const float* __restrict__ bd,
    float* __restrict__ out)
{
    extern __shared__ char smraw[];
    float*         bufF = (float*)(smraw + OFF_BUFF);          // [128][68] fp32
    __nv_bfloat16* actH = (__nv_bfloat16*)(smraw + OFF_ACTH);  // [128][72]
    __nv_bfloat16* actL = (__nv_bfloat16*)(smraw + OFF_ACTL);
    __nv_bfloat16* dvH  = (__nv_bfloat16*)(smraw + OFF_DVH);   // [128][40]
    __nv_bfloat16* dvL  = (__nv_bfloat16*)(smraw + OFF_DVL);
    float*         brep = (float*)(smraw + OFF_BREP);          // [16][68]

    const int t  = threadIdx.x;
    const int w  = t >> 5;
    const int ib = blockIdx.x * PPB;

    // ---- Stage enc: fp32 gather -> split -> bf16 hi/lo ----
    for (int k = t; k < 8 * PPB; k += BLOCK) {
        const int fg = k >> 7;
        const int p  = k & (PPB - 1);
        const unsigned gp = (unsigned)(ib + p);
        const int f = 4 * fg;
        float4 v;
        v.x = g_enc[(unsigned)(f    ) * N_PTS + gp];
        v.y = g_enc[(unsigned)(f + 1) * N_PTS + gp];
        v.z = g_enc[(unsigned)(f + 2) * N_PTS + gp];
        v.w = g_enc[(unsigned)(f + 3) * N_PTS + gp];
        split4_store(v, actH + p * LDAB + f, actL + p * LDAB + f);
    }

    // ---- Direction encode -> dvH/dvL[pt][0..31] (cols 27..31 zero) ----
    {
        const int pt = t & (PPB - 1);
        const int hf = t >> 7;
        const int i  = ib + pt;
        __nv_bfloat16* rh = dvH + pt * LDDV;
        __nv_bfloat16* rl = dvL + pt * LDDV;
        const float fr[4] = {1.f, 2.5198421f, 6.3496042f, 16.f};
        if (hf == 0) {
            const float dx = dir[3 * i], dy = dir[3 * i + 1];
            const float tx = 6.2831855f * dx, ty = 6.2831855f * dy;
            #pragma unroll
            for (int k = 0; k < 4; k++) {
                float s, c;
                sincosf(tx * fr[k], &s, &c);
                split1(s, rh[k],      rl[k]);
                split1(c, rh[12 + k], rl[12 + k]);
                sincosf(ty * fr[k], &s, &c);
                split1(s, rh[4 + k],  rl[4 + k]);
                split1(c, rh[16 + k], rl[16 + k]);
            }
        } else {
            const float dx = dir[3 * i], dy = dir[3 * i + 1], dz = dir[3 * i + 2];
            const float tz = 6.2831855f * dz;
            #pragma unroll
            for (int k = 0; k < 4; k++) {
                float s, c;
                sincosf(tz * fr[k], &s, &c);
                split1(s, rh[8 + k],  rl[8 + k]);
                split1(c, rh[20 + k], rl[20 + k]);
            }
            split1(dx, rh[24], rl[24]);
            split1(dy, rh[25], rl[25]);
            split1(dz, rh[26], rl[26]);
            #pragma unroll
            for (int k = 27; k < 32; k++) {
                rh[k] = __float2bfloat16_rn(0.f);
                rl[k] = __float2bfloat16_rn(0.f);
            }
        }
    }
    // ---- brep <- b0 ----
    for (int k = t; k < 16 * 64; k += BLOCK)
        brep[(k >> 6) * LDF + (k & 63)] = __ldg(&b0[k & 63]);
    __syncthreads();

    // ---- Layer 0: [128x32] @ w0 + b0, relu -> bufF ----
    bf16_layer64<32, true>(actH, actL, g_w0h, g_w0l, bufF, brep, w);
    __syncthreads();
    // bufF -> actH/L split; brep <- b1
    for (int k = t; k < 16 * PPB; k += BLOCK) {
        const int p = k & 127, fg = k >> 7;
        float4 v = *(float4*)(bufF + p * LDF + 4 * fg);
        split4_store(v, actH + p * LDAB + 4 * fg, actL + p * LDAB + 4 * fg);
    }
    for (int k = t; k < 16 * 64; k += BLOCK)
        brep[(k >> 6) * LDF + (k & 63)] = __ldg(&b1[k & 63]);
    __syncthreads();

    // ---- Layer 1: [128x64] @ w1 + b1, relu -> bufF ----
    bf16_layer64<64, true>(actH, actL, g_w1h, g_w1l, bufF, brep, w);
    __syncthreads();
    for (int k = t; k < 16 * PPB; k += BLOCK) {
        const int p = k & 127, fg = k >> 7;
        float4 v = *(float4*)(bufF + p * LDF + 4 * fg);
        split4_store(v, actH + p * LDAB + 4 * fg, actL + p * LDAB + 4 * fg);
    }
    for (int k = t; k < 16 * 64; k += BLOCK)
        brep[(k >> 6) * LDF + (k & 63)] = __ldg(&b2[k & 63]);
    __syncthreads();

    // ---- Layer 2: [128x64] @ w2 + b2, linear -> bufF (= bp fp32) ----
    bf16_layer64<64, false>(actH, actL, g_w2h, g_w2l, bufF, brep, w);
    __syncthreads();
    // bp fp32 -> actH/L (for head MMA); density tail reads bp fp32 NOW.
    for (int k = t; k < 16 * PPB; k += BLOCK) {
        const int p = k & 127, fg = k >> 7;
        float4 v = *(float4*)(bufF + p * LDF + 4 * fg);
        split4_store(v, actH + p * LDAB + 4 * fg, actL + p * LDAB + 4 * fg);
    }
    if (t < PPB) {
        // density = softplus(bp @ wd + bd)
        const float* r = bufF + t * LDF;
        float a = __ldg(&bd[0]);
        #pragma unroll
        for (int q = 0; q < 16; q++) {
            const float4 v = *(const float4*)(r + 4 * q);
            a = fmaf(v.x, __ldg(&wd[4 * q + 0]), a);
            a = fmaf(v.y, __ldg(&wd[4 * q + 1]), a);
            a = fmaf(v.z, __ldg(&wd[4 * q + 2]), a);
            a = fmaf(v.w, __ldg(&wd[4 * q + 3]), a);
        }
        out[4 * (ib + t) + 3] = fmaxf(a, 0.f) + log1pf(expf(-fabsf(a)));
    }
    // brep <- br (32 wide)
    for (int k = t; k < 16 * 32; k += BLOCK)
        brep[(k >> 5) * LDF + (k & 31)] = __ldg(&br[k & 31]);
    __syncthreads();

    // ---- RGB head MMA: rgbh -> bufF[pt][0..31] ----
    bf16_head(actH, actL, dvH, dvL, bufF, brep, w);
    __syncthreads();

    // ---- rgb tail ----
    if (t < PPB) {
        const int ii = ib + t;
        const float* r = bufF + t * LDF;
        float a0 = __ldg(&bc[0]), a1 = __ldg(&bc[1]), a2 = __ldg(&bc[2]);
        #pragma unroll
        for (int q = 0; q < 8; q++) {
            const float4 v = *(const float4*)(r + 4 * q);
            #pragma unroll
            for (int j = 0; j < 4; j++) {
                const float x = (&v.x)[j];
                const int kk = 4 * q + j;
                a0 = fmaf(x, __ldg(&wc[kk * 3 + 0]), a0);
                a1 = fmaf(x, __ldg(&wc[kk * 3 + 1]), a1);
                a2 = fmaf(x, __ldg(&wc[kk * 3 + 2]), a2);
            }
        }
        out[4 * ii + 0] = 1.f / (1.f + expf(-a0));
        out[4 * ii + 1] = 1.f / (1.f + expf(-a1));
        out[4 * ii + 2] = 1.f / (1.f + expf(-a2));
    }
}

extern "C" void kernel_launch(void* const* d_in, const int* in_sizes, int n_in,
                              void* d_out, int out_size) {
    (void)in_sizes; (void)n_in; (void)out_size;
    const float*  pos = (const float*)d_in[0];
    const float*  dir = (const float*)d_in[1];
    const float2* tab = (const float2*)d_in[2];
    const float *w0 = (const float*)d_in[3],  *b0 = (const float*)d_in[4];
    const float *w1 = (const float*)d_in[5],  *b1 = (const float*)d_in[6];
    const float *w2 = (const float*)d_in[7],  *b2 = (const float*)d_in[8];
    const float *wr = (const float*)d_in[9],  *br = (const float*)d_in[10];
    const float *wc = (const float*)d_in[11], *bc = (const float*)d_in[12];
    const float *wd = (const float*)d_in[13], *bd = (const float*)d_in[14];
    float* out = (float*)d_out;

    split_kernel<<<8, 256>>>(w0, w1, w2, wr);
    encode_kernel<<<(16 * N_PTS) / 256, 256>>>(pos, tab);

    cudaFuncSetAttribute(mlp_kernel,
                         cudaFuncAttributeMaxDynamicSharedMemorySize, SMEM_BYTES);
    mlp_kernel<<<N_PTS / PPB, BLOCK, SMEM_BYTES>>>(
        dir, b0, b1, b2, br, wc, bc, wd, bd, out);
}